// round 3
// baseline (speedup 1.0000x reference)
#include <cuda_runtime.h>
#include <cuda_bf16.h>

// velocity = MLP(concat(zone_embedding, person_attrs, time_vec)).
// GCN layers are dead code w.r.t. the output; person/time layer-1
// contributions are row-constant, folded into g_c1 by setup_kernel.
//
// R3: all smem weight reads widened to LDS.128 (ld.shared.v2.b64) — halves
// the L1TEX wavefront count that R2's ncu showed as the binding pipe.
// launch_bounds(128,5) for 20 warps/SM.

#define HID 32
#define H1  64

typedef unsigned long long u64;

__device__ float g_c1[H1];

__device__ __forceinline__ u64 fma2(u64 a, u64 b, u64 c) {
    u64 d;
    asm("fma.rn.f32x2 %0, %1, %2, %3;" : "=l"(d) : "l"(a), "l"(b), "l"(c));
    return d;
}
__device__ __forceinline__ u64 dup2(float x) {
    u64 d;
    asm("mov.b64 %0, {%1, %1};" : "=l"(d) : "f"(x));
    return d;
}
__device__ __forceinline__ float2 unpk2(u64 v) {
    float2 r;
    asm("mov.b64 {%0, %1}, %2;" : "=f"(r.x), "=f"(r.y) : "l"(v));
    return r;
}

// ---------------------------------------------------------------------------
__global__ void setup_kernel(const float* __restrict__ t,
                             const float* __restrict__ pa,
                             const float* __restrict__ Wt1, const float* __restrict__ bt1,
                             const float* __restrict__ Wt2, const float* __restrict__ bt2,
                             const float* __restrict__ Wd1, const float* __restrict__ bd1)
{
    __shared__ float u[16];
    __shared__ float tv[16];
    const int j = threadIdx.x;

    if (j < 16) u[j] = fmaxf(fmaf(t[0], Wt1[j], bt1[j]), 0.0f);
    __syncthreads();

    if (j < 16) {
        float a = bt2[j];
        #pragma unroll
        for (int i = 0; i < 16; i++) a = fmaf(u[i], Wt2[i * 16 + j], a);
        tv[j] = a;
    }
    __syncthreads();

    if (j < H1) {
        float a = bd1[j];
        #pragma unroll
        for (int p = 0; p < 8; p++)  a = fmaf(pa[p], Wd1[(HID + p) * H1 + j], a);
        #pragma unroll
        for (int i = 0; i < 16; i++) a = fmaf(tv[i], Wd1[(HID + 8 + i) * H1 + j], a);
        g_c1[j] = a;
    }
}

// ---------------------------------------------------------------------------
// One thread per row. Weights in smem as f32x2 pairs (native row-major is
// j-contiguous so pairs need no transpose); all reads are 16B LDS.128,
// warp-uniform (broadcast, conflict-free).
// ---------------------------------------------------------------------------
__global__ __launch_bounds__(128, 5)
void mlp_kernel(const float* __restrict__ emb,
                const float* __restrict__ Wd1,
                const float* __restrict__ Wd2, const float* __restrict__ bd2,
                const float* __restrict__ Wd3, const float* __restrict__ bd3,
                float* __restrict__ out, int nrows)
{
    __shared__ __align__(16) u64 sW1u[32 * 32];   // [k][j2]  layer1 zone part
    __shared__ __align__(16) u64 sW2u[64 * 16];   // [k][j2]
    __shared__ __align__(16) u64 sW3u[32 * 16];   // [k][j2]
    __shared__ __align__(16) u64 sC1u[32];
    __shared__ __align__(16) u64 sB2u[16], sB3u[16];

    const int tid = threadIdx.x;

    {
        const u64* w1 = reinterpret_cast<const u64*>(Wd1);   // zone rows = first 1024 u64
        const u64* w2 = reinterpret_cast<const u64*>(Wd2);
        const u64* w3 = reinterpret_cast<const u64*>(Wd3);
        for (int i = tid; i < 1024; i += 128) sW1u[i] = w1[i];
        for (int i = tid; i < 1024; i += 128) sW2u[i] = w2[i];
        for (int i = tid; i <  512; i += 128) sW3u[i] = w3[i];
        const u64* c1 = reinterpret_cast<const u64*>(g_c1);
        const u64* b2 = reinterpret_cast<const u64*>(bd2);
        const u64* b3 = reinterpret_cast<const u64*>(bd3);
        if (tid < 32) sC1u[tid] = c1[tid];
        if (tid < 16) { sB2u[tid] = b2[tid]; sB3u[tid] = b3[tid]; }
    }
    __syncthreads();

    const int row = blockIdx.x * 128 + tid;
    if (row >= nrows) return;

    // Embedding row (coalesced float4 loads).
    float z[HID];
    {
        const float4* zp = reinterpret_cast<const float4*>(emb + (size_t)row * HID);
        #pragma unroll
        for (int q = 0; q < 8; q++) {
            float4 v = zp[q];
            z[4*q+0] = v.x; z[4*q+1] = v.y; z[4*q+2] = v.z; z[4*q+3] = v.w;
        }
    }

    // Layer-2 accumulators (32 floats as 16 pairs), init with bias.
    u64 acc2[16];
    {
        const ulonglong2* b = reinterpret_cast<const ulonglong2*>(sB2u);
        #pragma unroll
        for (int q = 0; q < 8; q++) {
            ulonglong2 v = b[q];
            acc2[2*q] = v.x; acc2[2*q+1] = v.y;
        }
    }

    // Fused layer1 (chunks of 16 outputs) -> relu -> layer2 accumulate.
    #pragma unroll
    for (int c = 0; c < 4; c++) {
        u64 acc1[8];
        {
            const ulonglong2* cc = reinterpret_cast<const ulonglong2*>(sC1u + c * 8);
            #pragma unroll
            for (int q = 0; q < 4; q++) {
                ulonglong2 v = cc[q];
                acc1[2*q] = v.x; acc1[2*q+1] = v.y;
            }
        }

        #pragma unroll
        for (int k = 0; k < 32; k++) {
            u64 zz = dup2(z[k]);
            const ulonglong2* w = reinterpret_cast<const ulonglong2*>(sW1u + k * 32 + c * 8);
            #pragma unroll
            for (int q = 0; q < 4; q++) {
                ulonglong2 ww = w[q];
                acc1[2*q]   = fma2(ww.x, zz, acc1[2*q]);
                acc1[2*q+1] = fma2(ww.y, zz, acc1[2*q+1]);
            }
        }

        #pragma unroll
        for (int p = 0; p < 8; p++) {
            float2 h = unpk2(acc1[p]);
            const int k0 = c * 16 + 2 * p;
            u64 hh0 = dup2(fmaxf(h.x, 0.0f));
            u64 hh1 = dup2(fmaxf(h.y, 0.0f));
            const ulonglong2* w0 = reinterpret_cast<const ulonglong2*>(sW2u + (k0 + 0) * 16);
            const ulonglong2* w1 = reinterpret_cast<const ulonglong2*>(sW2u + (k0 + 1) * 16);
            #pragma unroll
            for (int q = 0; q < 8; q++) {
                ulonglong2 a0 = w0[q];
                ulonglong2 a1 = w1[q];
                u64 t0 = fma2(a0.x, hh0, acc2[2*q]);
                u64 t1 = fma2(a0.y, hh0, acc2[2*q+1]);
                acc2[2*q]   = fma2(a1.x, hh1, t0);
                acc2[2*q+1] = fma2(a1.y, hh1, t1);
            }
        }
    }

    // Layer 3: relu(acc2) -> 32 outs, linear.
    u64 acc3[16];
    {
        const ulonglong2* b = reinterpret_cast<const ulonglong2*>(sB3u);
        #pragma unroll
        for (int q = 0; q < 8; q++) {
            ulonglong2 v = b[q];
            acc3[2*q] = v.x; acc3[2*q+1] = v.y;
        }
    }

    #pragma unroll
    for (int q = 0; q < 16; q++) {
        float2 h = unpk2(acc2[q]);
        const int k0 = 2 * q;
        u64 hh0 = dup2(fmaxf(h.x, 0.0f));
        u64 hh1 = dup2(fmaxf(h.y, 0.0f));
        const ulonglong2* w0 = reinterpret_cast<const ulonglong2*>(sW3u + (k0 + 0) * 16);
        const ulonglong2* w1 = reinterpret_cast<const ulonglong2*>(sW3u + (k0 + 1) * 16);
        #pragma unroll
        for (int p = 0; p < 8; p++) {
            ulonglong2 a0 = w0[p];
            ulonglong2 a1 = w1[p];
            u64 t0 = fma2(a0.x, hh0, acc3[2*p]);
            u64 t1 = fma2(a0.y, hh0, acc3[2*p+1]);
            acc3[2*p]   = fma2(a1.x, hh1, t0);
            acc3[2*p+1] = fma2(a1.y, hh1, t1);
        }
    }

    // Store 32 floats = 8 x 128-bit.
    ulonglong2* op = reinterpret_cast<ulonglong2*>(out + (size_t)row * HID);
    #pragma unroll
    for (int p = 0; p < 8; p++) {
        ulonglong2 v;
        v.x = acc3[2 * p];
        v.y = acc3[2 * p + 1];
        op[p] = v;
    }
}

extern "C" void kernel_launch(void* const* d_in, const int* in_sizes, int n_in,
                              void* d_out, int out_size)
{
    const float* t   = (const float*)d_in[0];
    const float* emb = (const float*)d_in[1];
    const float* pa  = (const float*)d_in[3];
    const float* Wt1 = (const float*)d_in[9];
    const float* bt1 = (const float*)d_in[10];
    const float* Wt2 = (const float*)d_in[11];
    const float* bt2 = (const float*)d_in[12];
    const float* Wd1 = (const float*)d_in[13];
    const float* bd1 = (const float*)d_in[14];
    const float* Wd2 = (const float*)d_in[15];
    const float* bd2 = (const float*)d_in[16];
    const float* Wd3 = (const float*)d_in[17];
    const float* bd3 = (const float*)d_in[18];
    float* out = (float*)d_out;

    const int nrows = in_sizes[1] / HID;

    setup_kernel<<<1, 64>>>(t, pa, Wt1, bt1, Wt2, bt2, Wd1, bd1);
    mlp_kernel<<<(nrows + 127) / 128, 128>>>(emb, Wd1, Wd2, bd2, Wd3, bd3, out, nrows);
}